// round 1
// baseline (speedup 1.0000x reference)
#include <cuda_runtime.h>
#include <cstdint>

// Problem dims
#define BB 4
#define SS 2048
#define DD 1024
#define HH 64
#define MTOT (BB * SS)   // 8192

// Scratch (device globals — no allocation allowed)
__device__ float g_q [MTOT * HH];                 // 2 MB
__device__ float g_k [MTOT * HH];                 // 2 MB
__device__ float g_xv[MTOT * HH];                 // 2 MB
__device__ float g_x [(size_t)MTOT * DD];         // 32 MB
__device__ float g_P [(size_t)BB * SS * SS];      // 64 MB

// ---------------------------------------------------------------------------
// Kernel 1: fused projections. z=0 -> q = X@Q, z=1 -> k = X@K, z=2 -> xv = X@V
// GEMM [8192,1024] @ [1024,64]; 64x64 block tile, BK=16, 4x4 per-thread.
// ---------------------------------------------------------------------------
__global__ void __launch_bounds__(256) proj_kernel(
    const float* __restrict__ X,
    const float* __restrict__ Wq,
    const float* __restrict__ Wk,
    const float* __restrict__ Wv)
{
    __shared__ float Xs[64][16];
    __shared__ float Ws[16][64];

    const int tid = threadIdx.x;
    const int m0  = blockIdx.x * 64;
    const float* W   = (blockIdx.z == 0) ? Wq : (blockIdx.z == 1) ? Wk : Wv;
    float*       out = (blockIdx.z == 0) ? g_q : (blockIdx.z == 1) ? g_k : g_xv;

    const int tx = tid & 15;        // 0..15 -> cols (h)
    const int ty = tid >> 4;        // 0..15 -> rows (m)

    float acc[4][4] = {};

    for (int k0 = 0; k0 < DD; k0 += 16) {
        // X tile: 64 rows x 16 k  (one float4 per thread)
        {
            int r = tid >> 2;
            int c = (tid & 3) * 4;
            float4 v = *(const float4*)(X + (size_t)(m0 + r) * DD + k0 + c);
            Xs[r][c + 0] = v.x; Xs[r][c + 1] = v.y;
            Xs[r][c + 2] = v.z; Xs[r][c + 3] = v.w;
        }
        // W tile: 16 k x 64 h  (one float4 per thread)
        {
            int r = tid >> 4;
            int c = (tid & 15) * 4;
            float4 v = *(const float4*)(W + (size_t)(k0 + r) * HH + c);
            Ws[r][c + 0] = v.x; Ws[r][c + 1] = v.y;
            Ws[r][c + 2] = v.z; Ws[r][c + 3] = v.w;
        }
        __syncthreads();

        #pragma unroll
        for (int kk = 0; kk < 16; kk++) {
            float a[4];
            #pragma unroll
            for (int i = 0; i < 4; i++) a[i] = Xs[ty * 4 + i][kk];
            float4 bv = *(const float4*)&Ws[kk][tx * 4];
            float b[4] = {bv.x, bv.y, bv.z, bv.w};
            #pragma unroll
            for (int i = 0; i < 4; i++)
                #pragma unroll
                for (int j = 0; j < 4; j++)
                    acc[i][j] = fmaf(a[i], b[j], acc[i][j]);
        }
        __syncthreads();
    }

    #pragma unroll
    for (int i = 0; i < 4; i++) {
        float4 v = {acc[i][0], acc[i][1], acc[i][2], acc[i][3]};
        *(float4*)(out + (size_t)(m0 + ty * 4 + i) * HH + tx * 4) = v;
    }
}

// ---------------------------------------------------------------------------
// Kernel 2: x = xv @ O^T.  [8192,64] @ [64,1024] -> [8192,1024]
// 64x64 tile, K=64 fully resident, 4x4 per-thread.
// ---------------------------------------------------------------------------
__global__ void __launch_bounds__(256) xo_kernel(const float* __restrict__ O)
{
    __shared__ float Av[64][64];
    __shared__ float Bo[64][65];   // padded: col-major-ish reads conflict-free

    const int tid = threadIdx.x;
    const int e0  = blockIdx.x * 64;
    const int m0  = blockIdx.y * 64;

    for (int idx = tid; idx < 64 * 64; idx += 256) {
        int r = idx >> 6, c = idx & 63;
        Av[r][c] = g_xv[(size_t)(m0 + r) * HH + c];
        Bo[r][c] = O   [(size_t)(e0 + r) * HH + c];
    }
    __syncthreads();

    const int tx = tid & 15, ty = tid >> 4;
    float acc[4][4] = {};

    #pragma unroll 8
    for (int h = 0; h < 64; h++) {
        float a[4], b[4];
        #pragma unroll
        for (int i = 0; i < 4; i++) a[i] = Av[ty * 4 + i][h];
        #pragma unroll
        for (int j = 0; j < 4; j++) b[j] = Bo[tx * 4 + j][h];
        #pragma unroll
        for (int i = 0; i < 4; i++)
            #pragma unroll
            for (int j = 0; j < 4; j++)
                acc[i][j] = fmaf(a[i], b[j], acc[i][j]);
    }

    #pragma unroll
    for (int i = 0; i < 4; i++) {
        float4 v = {acc[i][0], acc[i][1], acc[i][2], acc[i][3]};
        *(float4*)(g_x + (size_t)(m0 + ty * 4 + i) * DD + e0 + tx * 4) = v;
    }
}

// ---------------------------------------------------------------------------
// Kernel 3: causal raw scores  P[b,i,j] = q[b,i,:] . k[b,j,:]   (j <= i only)
// Only lower-triangular 64x64 blocks are computed; other entries are handled
// by the softmax kernel's zero-fill.
// ---------------------------------------------------------------------------
__global__ void __launch_bounds__(256) scores_kernel()
{
    const int jt = blockIdx.x, it = blockIdx.y, b = blockIdx.z;
    if (jt > it) return;

    __shared__ float Qs[64][64];
    __shared__ float Ks[64][65];

    const int tid = threadIdx.x;
    const int i0 = it * 64, j0 = jt * 64;
    const int base = b * SS;

    for (int idx = tid; idx < 64 * 64; idx += 256) {
        int r = idx >> 6, c = idx & 63;
        Qs[r][c] = g_q[(size_t)(base + i0 + r) * HH + c];
        Ks[r][c] = g_k[(size_t)(base + j0 + r) * HH + c];
    }
    __syncthreads();

    const int tx = tid & 15, ty = tid >> 4;
    float acc[4][4] = {};

    #pragma unroll 8
    for (int h = 0; h < 64; h++) {
        float a[4], bb[4];
        #pragma unroll
        for (int i = 0; i < 4; i++) a[i]  = Qs[ty * 4 + i][h];
        #pragma unroll
        for (int j = 0; j < 4; j++) bb[j] = Ks[tx * 4 + j][h];
        #pragma unroll
        for (int i = 0; i < 4; i++)
            #pragma unroll
            for (int j = 0; j < 4; j++)
                acc[i][j] = fmaf(a[i], bb[j], acc[i][j]);
    }

    float* Pb = g_P + (size_t)b * SS * SS;
    #pragma unroll
    for (int i = 0; i < 4; i++) {
        int gi = i0 + ty * 4 + i;
        #pragma unroll
        for (int j = 0; j < 4; j++) {
            int gj = j0 + tx * 4 + j;
            if (gj <= gi)
                Pb[(size_t)gi * SS + gj] = acc[i][j];
        }
    }
}

// ---------------------------------------------------------------------------
// Kernel 4: row softmax over P[b,q,0..q], then zero-fill pad up to the next
// 128-boundary so the P@x GEMM needs no masking (unwritten garbage never read).
// ---------------------------------------------------------------------------
__global__ void __launch_bounds__(256) softmax_kernel()
{
    const int g = blockIdx.x;           // 0..8191 : (b*S + q)
    const int q = g & (SS - 1);
    float* row = g_P + (size_t)g * SS;
    const int len  = q + 1;
    const int kend = ((q >> 7) + 1) << 7;   // round len up to 128

    __shared__ float buf[SS];
    __shared__ float red[256];
    const int tid = threadIdx.x;

    float mx = -3.0e38f;
    for (int i = tid; i < len; i += 256) {
        float v = row[i];
        buf[i] = v;
        mx = fmaxf(mx, v);
    }
    red[tid] = mx;
    __syncthreads();
    for (int s = 128; s > 0; s >>= 1) {
        if (tid < s) red[tid] = fmaxf(red[tid], red[tid + s]);
        __syncthreads();
    }
    const float m = red[0];
    __syncthreads();

    float sm = 0.f;
    for (int i = tid; i < len; i += 256) {
        float e = expf(buf[i] - m);
        buf[i] = e;
        sm += e;
    }
    red[tid] = sm;
    __syncthreads();
    for (int s = 128; s > 0; s >>= 1) {
        if (tid < s) red[tid] += red[tid + s];
        __syncthreads();
    }
    const float inv = 1.0f / red[0];

    for (int i = tid; i < len; i += 256)       row[i] = buf[i] * inv;
    for (int i = len + tid; i < kend; i += 256) row[i] = 0.0f;
}

// ---------------------------------------------------------------------------
// Kernel 5: out[b] = P[b] @ x[b].  Per batch: [2048,2048] @ [2048,1024].
// 128x128 block tile, BK=16, 8x8 per-thread, causal K-bound per row tile.
// ---------------------------------------------------------------------------
__global__ void __launch_bounds__(256) pv_kernel(float* __restrict__ out)
{
    __shared__ float As[16][132];   // A transposed; 132 keeps float4 align + good banks
    __shared__ float Bs[16][128];

    const int tid = threadIdx.x;
    const int n0  = blockIdx.x * 128;
    const int m0  = blockIdx.y * 128;
    const int b   = blockIdx.z;

    const float* P  = g_P + (size_t)b * SS * SS;
    const float* Xb = g_x + (size_t)b * SS * DD;

    const int tx = tid & 15, ty = tid >> 4;
    const int row = ty * 8, col = tx * 8;

    float acc[8][8] = {};
    const int kend = m0 + 128;   // causal: rows in this tile only attend to k < m0+128

    for (int kt = 0; kt < kend; kt += 16) {
        // A tile (P): 128 rows x 16 k, stored transposed
        #pragma unroll
        for (int it = 0; it < 2; it++) {
            int r = (tid >> 2) + it * 64;
            int c = (tid & 3) * 4;
            float4 v = *(const float4*)(P + (size_t)(m0 + r) * SS + kt + c);
            As[c + 0][r] = v.x;
            As[c + 1][r] = v.y;
            As[c + 2][r] = v.z;
            As[c + 3][r] = v.w;
        }
        // B tile (x): 16 k x 128 n
        #pragma unroll
        for (int it = 0; it < 2; it++) {
            int r = (tid >> 5) + it * 8;
            int c = (tid & 31) * 4;
            *(float4*)&Bs[r][c] = *(const float4*)(Xb + (size_t)(kt + r) * DD + n0 + c);
        }
        __syncthreads();

        #pragma unroll
        for (int kk = 0; kk < 16; kk++) {
            float4 a0 = *(const float4*)&As[kk][row];
            float4 a1 = *(const float4*)&As[kk][row + 4];
            float4 b0 = *(const float4*)&Bs[kk][col];
            float4 b1 = *(const float4*)&Bs[kk][col + 4];
            float a[8] = {a0.x, a0.y, a0.z, a0.w, a1.x, a1.y, a1.z, a1.w};
            float bv[8] = {b0.x, b0.y, b0.z, b0.w, b1.x, b1.y, b1.z, b1.w};
            #pragma unroll
            for (int i = 0; i < 8; i++)
                #pragma unroll
                for (int j = 0; j < 8; j++)
                    acc[i][j] = fmaf(a[i], bv[j], acc[i][j]);
        }
        __syncthreads();
    }

    float* orow = out + (size_t)(b * SS + m0 + row) * DD + n0 + col;
    #pragma unroll
    for (int i = 0; i < 8; i++) {
        float4 v0 = {acc[i][0], acc[i][1], acc[i][2], acc[i][3]};
        float4 v1 = {acc[i][4], acc[i][5], acc[i][6], acc[i][7]};
        *(float4*)(orow + (size_t)i * DD)     = v0;
        *(float4*)(orow + (size_t)i * DD + 4) = v1;
    }
}

// ---------------------------------------------------------------------------
// Host launch (graph-capturable: kernel launches only)
// ---------------------------------------------------------------------------
extern "C" void kernel_launch(void* const* d_in, const int* in_sizes, int n_in,
                              void* d_out, int out_size)
{
    const float* X  = (const float*)d_in[0];
    const float* Wq = (const float*)d_in[1];
    const float* Wk = (const float*)d_in[2];
    const float* Wv = (const float*)d_in[3];
    const float* Wo = (const float*)d_in[4];
    float* out = (float*)d_out;

    proj_kernel   <<<dim3(MTOT / 64, 1, 3), 256>>>(X, Wq, Wk, Wv);
    xo_kernel     <<<dim3(DD / 64, MTOT / 64), 256>>>(Wo);
    scores_kernel <<<dim3(SS / 64, SS / 64, BB), 256>>>();
    softmax_kernel<<<MTOT, 256>>>();
    pv_kernel     <<<dim3(DD / 128, SS / 128, BB), 256>>>(out);
}

// round 2
// speedup vs baseline: 1.5642x; 1.5642x over previous
#include <cuda_runtime.h>
#include <cstdint>

// Problem dims
#define BB 4
#define SS 2048
#define DD 1024
#define HH 64
#define MTOT (BB * SS)   // 8192

// Scratch (device globals — no allocation allowed)
__device__ float g_q [MTOT * HH];                 // 2 MB
__device__ float g_k [MTOT * HH];                 // 2 MB
__device__ float g_xv[MTOT * HH];                 // 2 MB
__device__ float g_x [(size_t)MTOT * DD];         // 32 MB
__device__ float g_P [(size_t)BB * SS * SS];      // 64 MB

__device__ __forceinline__ uint32_t f2tf32(float f) {
    uint32_t u;
    asm("cvt.rna.tf32.f32 %0, %1;" : "=r"(u) : "f"(f));
    return u;
}

// ---------------------------------------------------------------------------
// Kernel 1: fused projections. z=0 -> q = X@Q, z=1 -> k = X@K, z=2 -> xv = X@V
// ---------------------------------------------------------------------------
__global__ void __launch_bounds__(256) proj_kernel(
    const float* __restrict__ X,
    const float* __restrict__ Wq,
    const float* __restrict__ Wk,
    const float* __restrict__ Wv)
{
    __shared__ float Xs[64][16];
    __shared__ float Ws[16][64];

    const int tid = threadIdx.x;
    const int m0  = blockIdx.x * 64;
    const float* W   = (blockIdx.z == 0) ? Wq : (blockIdx.z == 1) ? Wk : Wv;
    float*       out = (blockIdx.z == 0) ? g_q : (blockIdx.z == 1) ? g_k : g_xv;

    const int tx = tid & 15;
    const int ty = tid >> 4;

    float acc[4][4] = {};

    for (int k0 = 0; k0 < DD; k0 += 16) {
        {
            int r = tid >> 2;
            int c = (tid & 3) * 4;
            float4 v = *(const float4*)(X + (size_t)(m0 + r) * DD + k0 + c);
            Xs[r][c + 0] = v.x; Xs[r][c + 1] = v.y;
            Xs[r][c + 2] = v.z; Xs[r][c + 3] = v.w;
        }
        {
            int r = tid >> 4;
            int c = (tid & 15) * 4;
            float4 v = *(const float4*)(W + (size_t)(k0 + r) * HH + c);
            Ws[r][c + 0] = v.x; Ws[r][c + 1] = v.y;
            Ws[r][c + 2] = v.z; Ws[r][c + 3] = v.w;
        }
        __syncthreads();

        #pragma unroll
        for (int kk = 0; kk < 16; kk++) {
            float a[4];
            #pragma unroll
            for (int i = 0; i < 4; i++) a[i] = Xs[ty * 4 + i][kk];
            float4 bv = *(const float4*)&Ws[kk][tx * 4];
            float b[4] = {bv.x, bv.y, bv.z, bv.w};
            #pragma unroll
            for (int i = 0; i < 4; i++)
                #pragma unroll
                for (int j = 0; j < 4; j++)
                    acc[i][j] = fmaf(a[i], b[j], acc[i][j]);
        }
        __syncthreads();
    }

    #pragma unroll
    for (int i = 0; i < 4; i++) {
        float4 v = {acc[i][0], acc[i][1], acc[i][2], acc[i][3]};
        *(float4*)(out + (size_t)(m0 + ty * 4 + i) * HH + tx * 4) = v;
    }
}

// ---------------------------------------------------------------------------
// Kernel 2: x = xv @ O^T.  [8192,64] @ [64,1024] -> [8192,1024]
// ---------------------------------------------------------------------------
__global__ void __launch_bounds__(256) xo_kernel(const float* __restrict__ O)
{
    __shared__ float Av[64][64];
    __shared__ float Bo[64][65];

    const int tid = threadIdx.x;
    const int e0  = blockIdx.x * 64;
    const int m0  = blockIdx.y * 64;

    for (int idx = tid; idx < 64 * 64; idx += 256) {
        int r = idx >> 6, c = idx & 63;
        Av[r][c] = g_xv[(size_t)(m0 + r) * HH + c];
        Bo[r][c] = O   [(size_t)(e0 + r) * HH + c];
    }
    __syncthreads();

    const int tx = tid & 15, ty = tid >> 4;
    float acc[4][4] = {};

    #pragma unroll 8
    for (int h = 0; h < 64; h++) {
        float a[4], b[4];
        #pragma unroll
        for (int i = 0; i < 4; i++) a[i] = Av[ty * 4 + i][h];
        #pragma unroll
        for (int j = 0; j < 4; j++) b[j] = Bo[tx * 4 + j][h];
        #pragma unroll
        for (int i = 0; i < 4; i++)
            #pragma unroll
            for (int j = 0; j < 4; j++)
                acc[i][j] = fmaf(a[i], b[j], acc[i][j]);
    }

    #pragma unroll
    for (int i = 0; i < 4; i++) {
        float4 v = {acc[i][0], acc[i][1], acc[i][2], acc[i][3]};
        *(float4*)(g_x + (size_t)(m0 + ty * 4 + i) * DD + e0 + tx * 4) = v;
    }
}

// ---------------------------------------------------------------------------
// Kernel 3: causal raw scores (fp32 for precision through exp)
// ---------------------------------------------------------------------------
__global__ void __launch_bounds__(256) scores_kernel()
{
    const int jt = blockIdx.x, it = blockIdx.y, b = blockIdx.z;
    if (jt > it) return;

    __shared__ float Qs[64][64];
    __shared__ float Ks[64][65];

    const int tid = threadIdx.x;
    const int i0 = it * 64, j0 = jt * 64;
    const int base = b * SS;

    for (int idx = tid; idx < 64 * 64; idx += 256) {
        int r = idx >> 6, c = idx & 63;
        Qs[r][c] = g_q[(size_t)(base + i0 + r) * HH + c];
        Ks[r][c] = g_k[(size_t)(base + j0 + r) * HH + c];
    }
    __syncthreads();

    const int tx = tid & 15, ty = tid >> 4;
    float acc[4][4] = {};

    #pragma unroll 8
    for (int h = 0; h < 64; h++) {
        float a[4], bb[4];
        #pragma unroll
        for (int i = 0; i < 4; i++) a[i]  = Qs[ty * 4 + i][h];
        #pragma unroll
        for (int j = 0; j < 4; j++) bb[j] = Ks[tx * 4 + j][h];
        #pragma unroll
        for (int i = 0; i < 4; i++)
            #pragma unroll
            for (int j = 0; j < 4; j++)
                acc[i][j] = fmaf(a[i], bb[j], acc[i][j]);
    }

    float* Pb = g_P + (size_t)b * SS * SS;
    #pragma unroll
    for (int i = 0; i < 4; i++) {
        int gi = i0 + ty * 4 + i;
        #pragma unroll
        for (int j = 0; j < 4; j++) {
            int gj = j0 + tx * 4 + j;
            if (gj <= gi)
                Pb[(size_t)gi * SS + gj] = acc[i][j];
        }
    }
}

// ---------------------------------------------------------------------------
// Kernel 4: row softmax + zero-fill pad up to next 128-boundary
// ---------------------------------------------------------------------------
__global__ void __launch_bounds__(256) softmax_kernel()
{
    const int g = blockIdx.x;
    const int q = g & (SS - 1);
    float* row = g_P + (size_t)g * SS;
    const int len  = q + 1;
    const int kend = ((q >> 7) + 1) << 7;

    __shared__ float buf[SS];
    __shared__ float red[256];
    const int tid = threadIdx.x;

    float mx = -3.0e38f;
    for (int i = tid; i < len; i += 256) {
        float v = row[i];
        buf[i] = v;
        mx = fmaxf(mx, v);
    }
    red[tid] = mx;
    __syncthreads();
    for (int s = 128; s > 0; s >>= 1) {
        if (tid < s) red[tid] = fmaxf(red[tid], red[tid + s]);
        __syncthreads();
    }
    const float m = red[0];
    __syncthreads();

    float sm = 0.f;
    for (int i = tid; i < len; i += 256) {
        float e = expf(buf[i] - m);
        buf[i] = e;
        sm += e;
    }
    red[tid] = sm;
    __syncthreads();
    for (int s = 128; s > 0; s >>= 1) {
        if (tid < s) red[tid] += red[tid + s];
        __syncthreads();
    }
    const float inv = 1.0f / red[0];

    for (int i = tid; i < len; i += 256)        row[i] = buf[i] * inv;
    for (int i = len + tid; i < kend; i += 256) row[i] = 0.0f;
}

// ---------------------------------------------------------------------------
// Kernel 5: out[b] = P[b] @ x[b] with mma.sync.m16n8k8 tf32 (fp32 accum).
// BM=BN=128, BK=32. 8 warps in 2x4; warp tile 64x32 (4 m-tiles x 4 n-tiles).
// A smem m-major [128][36] (pad 4 -> conflict-free frag reads & f4 stores),
// B smem k-major [32][136] (pad 8 -> conflict-free frag reads & f4 stores).
// ---------------------------------------------------------------------------
__global__ void __launch_bounds__(256) pv_mma_kernel(float* __restrict__ out)
{
    __shared__ float As[128][36];   // [m][k], pad 4
    __shared__ float Bs[32][136];   // [k][n], pad 8

    const int tid  = threadIdx.x;
    const int lane = tid & 31;
    const int wid  = tid >> 5;
    const int warp_m = wid >> 2;    // 0..1
    const int warp_n = wid & 3;     // 0..3

    const int n0 = blockIdx.x * 128;
    const int m0 = blockIdx.y * 128;
    const int b  = blockIdx.z;

    const float* P  = g_P + (size_t)b * SS * SS;
    const float* Xb = g_x + (size_t)b * SS * DD;

    const int lr = lane >> 2;       // 0..7
    const int lc = lane & 3;        // 0..3

    float acc[4][4][4] = {};        // [mt][nt][reg]

    const int kend = m0 + 128;      // causal bound (rows zero-padded to here)

    for (int kt = 0; kt < kend; kt += 32) {
        // A tile: P[m0..m0+127][kt..kt+31] -> As[m][k] as tf32 bits
        #pragma unroll
        for (int i = 0; i < 4; i++) {
            int idx = tid + i * 256;        // 0..1023
            int r = idx >> 3;               // m row 0..127
            int c = (idx & 7) * 4;          // k 0,4,...,28
            float4 v = *(const float4*)(P + (size_t)(m0 + r) * SS + kt + c);
            uint4 t;
            t.x = f2tf32(v.x); t.y = f2tf32(v.y);
            t.z = f2tf32(v.z); t.w = f2tf32(v.w);
            *(uint4*)&As[r][c] = t;
        }
        // B tile: Xb[kt..kt+31][n0..n0+127] -> Bs[k][n] as tf32 bits
        #pragma unroll
        for (int i = 0; i < 4; i++) {
            int idx = tid + i * 256;
            int r = idx >> 5;               // k 0..31
            int c = (idx & 31) * 4;         // n
            float4 v = *(const float4*)(Xb + (size_t)(kt + r) * DD + n0 + c);
            uint4 t;
            t.x = f2tf32(v.x); t.y = f2tf32(v.y);
            t.z = f2tf32(v.z); t.w = f2tf32(v.w);
            *(uint4*)&Bs[r][c] = t;
        }
        __syncthreads();

        #pragma unroll
        for (int ks = 0; ks < 32; ks += 8) {
            uint32_t afrag[4][4];
            #pragma unroll
            for (int mt = 0; mt < 4; mt++) {
                int mrow = warp_m * 64 + mt * 16 + lr;
                afrag[mt][0] = __float_as_uint(As[mrow    ][ks + lc    ]);
                afrag[mt][1] = __float_as_uint(As[mrow + 8][ks + lc    ]);
                afrag[mt][2] = __float_as_uint(As[mrow    ][ks + lc + 4]);
                afrag[mt][3] = __float_as_uint(As[mrow + 8][ks + lc + 4]);
            }
            uint32_t bfrag[4][2];
            #pragma unroll
            for (int nt = 0; nt < 4; nt++) {
                int ncol = warp_n * 32 + nt * 8 + lr;
                bfrag[nt][0] = __float_as_uint(Bs[ks + lc    ][ncol]);
                bfrag[nt][1] = __float_as_uint(Bs[ks + lc + 4][ncol]);
            }
            #pragma unroll
            for (int mt = 0; mt < 4; mt++) {
                #pragma unroll
                for (int nt = 0; nt < 4; nt++) {
                    asm volatile(
                        "mma.sync.aligned.m16n8k8.row.col.f32.tf32.tf32.f32 "
                        "{%0,%1,%2,%3}, {%4,%5,%6,%7}, {%8,%9}, {%0,%1,%2,%3};"
                        : "+f"(acc[mt][nt][0]), "+f"(acc[mt][nt][1]),
                          "+f"(acc[mt][nt][2]), "+f"(acc[mt][nt][3])
                        : "r"(afrag[mt][0]), "r"(afrag[mt][1]),
                          "r"(afrag[mt][2]), "r"(afrag[mt][3]),
                          "r"(bfrag[nt][0]), "r"(bfrag[nt][1]));
                }
            }
        }
        __syncthreads();
    }

    // Store: c0,c1 -> (m, 2lc), (m, 2lc+1); c2,c3 -> row m+8
    #pragma unroll
    for (int mt = 0; mt < 4; mt++) {
        int m = m0 + warp_m * 64 + mt * 16 + lr;
        #pragma unroll
        for (int nt = 0; nt < 4; nt++) {
            int n = n0 + warp_n * 32 + nt * 8 + lc * 2;
            float2 v0 = {acc[mt][nt][0], acc[mt][nt][1]};
            float2 v1 = {acc[mt][nt][2], acc[mt][nt][3]};
            *(float2*)(out + (size_t)(b * SS + m    ) * DD + n) = v0;
            *(float2*)(out + (size_t)(b * SS + m + 8) * DD + n) = v1;
        }
    }
}

// ---------------------------------------------------------------------------
// Host launch (graph-capturable: kernel launches only)
// ---------------------------------------------------------------------------
extern "C" void kernel_launch(void* const* d_in, const int* in_sizes, int n_in,
                              void* d_out, int out_size)
{
    const float* X  = (const float*)d_in[0];
    const float* Wq = (const float*)d_in[1];
    const float* Wk = (const float*)d_in[2];
    const float* Wv = (const float*)d_in[3];
    const float* Wo = (const float*)d_in[4];
    float* out = (float*)d_out;

    proj_kernel   <<<dim3(MTOT / 64, 1, 3), 256>>>(X, Wq, Wk, Wv);
    xo_kernel     <<<dim3(DD / 64, MTOT / 64), 256>>>(Wo);
    scores_kernel <<<dim3(SS / 64, SS / 64, BB), 256>>>();
    softmax_kernel<<<MTOT, 256>>>();
    pv_mma_kernel <<<dim3(DD / 128, SS / 128, BB), 256>>>(out);
}

// round 4
// speedup vs baseline: 2.0711x; 1.3241x over previous
#include <cuda_runtime.h>
#include <cstdint>

// Problem dims
#define BB 4
#define SS 2048
#define DD 1024
#define HH 64
#define MTOT (BB * SS)   // 8192

// Scratch (device globals — no allocation allowed)
__device__ float g_q [MTOT * HH];
__device__ float g_k [MTOT * HH];
__device__ float g_xv[MTOT * HH];
__device__ float g_x [(size_t)MTOT * DD];
__device__ float g_P [(size_t)BB * SS * SS];

__device__ __forceinline__ uint32_t f2tf32(float f) {
    uint32_t u;
    asm("cvt.rna.tf32.f32 %0, %1;" : "=r"(u) : "f"(f));
    return u;
}
__device__ __forceinline__ void mma_tf32(float* c, const uint32_t* a, const uint32_t* b) {
    asm volatile("mma.sync.aligned.m16n8k8.row.col.f32.tf32.tf32.f32 "
        "{%0,%1,%2,%3}, {%4,%5,%6,%7}, {%8,%9}, {%0,%1,%2,%3};"
        : "+f"(c[0]), "+f"(c[1]), "+f"(c[2]), "+f"(c[3])
        : "r"(a[0]), "r"(a[1]), "r"(a[2]), "r"(a[3]), "r"(b[0]), "r"(b[1]));
}

// ---------------------------------------------------------------------------
// Kernel 1: fused projections (round-2 known-good fp32 SIMT).
// z=0 -> q = X@Q, z=1 -> k = X@K, z=2 -> xv = X@V
// ---------------------------------------------------------------------------
__global__ void __launch_bounds__(256) proj_kernel(
    const float* __restrict__ X,
    const float* __restrict__ Wq,
    const float* __restrict__ Wk,
    const float* __restrict__ Wv)
{
    __shared__ float Xs[64][16];
    __shared__ float Ws[16][64];

    const int tid = threadIdx.x;
    const int m0  = blockIdx.x * 64;
    const float* W   = (blockIdx.z == 0) ? Wq : (blockIdx.z == 1) ? Wk : Wv;
    float*       out = (blockIdx.z == 0) ? g_q : (blockIdx.z == 1) ? g_k : g_xv;

    const int tx = tid & 15;
    const int ty = tid >> 4;

    float acc[4][4] = {};

    for (int k0 = 0; k0 < DD; k0 += 16) {
        {
            int r = tid >> 2;
            int c = (tid & 3) * 4;
            float4 v = *(const float4*)(X + (size_t)(m0 + r) * DD + k0 + c);
            Xs[r][c + 0] = v.x; Xs[r][c + 1] = v.y;
            Xs[r][c + 2] = v.z; Xs[r][c + 3] = v.w;
        }
        {
            int r = tid >> 4;
            int c = (tid & 15) * 4;
            float4 v = *(const float4*)(W + (size_t)(k0 + r) * HH + c);
            Ws[r][c + 0] = v.x; Ws[r][c + 1] = v.y;
            Ws[r][c + 2] = v.z; Ws[r][c + 3] = v.w;
        }
        __syncthreads();

        #pragma unroll
        for (int kk = 0; kk < 16; kk++) {
            float a[4];
            #pragma unroll
            for (int i = 0; i < 4; i++) a[i] = Xs[ty * 4 + i][kk];
            float4 bv = *(const float4*)&Ws[kk][tx * 4];
            float b[4] = {bv.x, bv.y, bv.z, bv.w};
            #pragma unroll
            for (int i = 0; i < 4; i++)
                #pragma unroll
                for (int j = 0; j < 4; j++)
                    acc[i][j] = fmaf(a[i], b[j], acc[i][j]);
        }
        __syncthreads();
    }

    #pragma unroll
    for (int i = 0; i < 4; i++) {
        float4 v = {acc[i][0], acc[i][1], acc[i][2], acc[i][3]};
        *(float4*)(out + (size_t)(m0 + ty * 4 + i) * HH + tx * 4) = v;
    }
}

// ---------------------------------------------------------------------------
// Kernel 2: x = xv @ O^T (round-2 known-good fp32 SIMT)
// ---------------------------------------------------------------------------
__global__ void __launch_bounds__(256) xo_kernel(const float* __restrict__ O)
{
    __shared__ float Av[64][64];
    __shared__ float Bo[64][65];

    const int tid = threadIdx.x;
    const int e0  = blockIdx.x * 64;
    const int m0  = blockIdx.y * 64;

    for (int idx = tid; idx < 64 * 64; idx += 256) {
        int r = idx >> 6, c = idx & 63;
        Av[r][c] = g_xv[(size_t)(m0 + r) * HH + c];
        Bo[r][c] = O   [(size_t)(e0 + r) * HH + c];
    }
    __syncthreads();

    const int tx = tid & 15, ty = tid >> 4;
    float acc[4][4] = {};

    #pragma unroll 8
    for (int h = 0; h < 64; h++) {
        float a[4], b[4];
        #pragma unroll
        for (int i = 0; i < 4; i++) a[i] = Av[ty * 4 + i][h];
        #pragma unroll
        for (int j = 0; j < 4; j++) b[j] = Bo[tx * 4 + j][h];
        #pragma unroll
        for (int i = 0; i < 4; i++)
            #pragma unroll
            for (int j = 0; j < 4; j++)
                acc[i][j] = fmaf(a[i], b[j], acc[i][j]);
    }

    #pragma unroll
    for (int i = 0; i < 4; i++) {
        float4 v = {acc[i][0], acc[i][1], acc[i][2], acc[i][3]};
        *(float4*)(g_x + (size_t)(m0 + ty * 4 + i) * DD + e0 + tx * 4) = v;
    }
}

// ---------------------------------------------------------------------------
// Kernel 3: causal raw scores (round-2 known-good fp32 SIMT)
// ---------------------------------------------------------------------------
__global__ void __launch_bounds__(256) scores_kernel()
{
    const int jt = blockIdx.x, it = blockIdx.y, b = blockIdx.z;
    if (jt > it) return;

    __shared__ float Qs[64][64];
    __shared__ float Ks[64][65];

    const int tid = threadIdx.x;
    const int i0 = it * 64, j0 = jt * 64;
    const int base = b * SS;

    for (int idx = tid; idx < 64 * 64; idx += 256) {
        int r = idx >> 6, c = idx & 63;
        Qs[r][c] = g_q[(size_t)(base + i0 + r) * HH + c];
        Ks[r][c] = g_k[(size_t)(base + j0 + r) * HH + c];
    }
    __syncthreads();

    const int tx = tid & 15, ty = tid >> 4;
    float acc[4][4] = {};

    #pragma unroll 8
    for (int h = 0; h < 64; h++) {
        float a[4], bb[4];
        #pragma unroll
        for (int i = 0; i < 4; i++) a[i]  = Qs[ty * 4 + i][h];
        #pragma unroll
        for (int j = 0; j < 4; j++) bb[j] = Ks[tx * 4 + j][h];
        #pragma unroll
        for (int i = 0; i < 4; i++)
            #pragma unroll
            for (int j = 0; j < 4; j++)
                acc[i][j] = fmaf(a[i], bb[j], acc[i][j]);
    }

    float* Pb = g_P + (size_t)b * SS * SS;
    #pragma unroll
    for (int i = 0; i < 4; i++) {
        int gi = i0 + ty * 4 + i;
        #pragma unroll
        for (int j = 0; j < 4; j++) {
            int gj = j0 + tx * 4 + j;
            if (gj <= gi)
                Pb[(size_t)gi * SS + gj] = acc[i][j];
        }
    }
}

// ---------------------------------------------------------------------------
// Kernel 4: row softmax + zero-fill pad (round-2 known-good, NO tf32 rounding)
// ---------------------------------------------------------------------------
__global__ void __launch_bounds__(256) softmax_kernel()
{
    const int g = blockIdx.x;
    const int q = g & (SS - 1);
    float* row = g_P + (size_t)g * SS;
    const int len  = q + 1;
    const int kend = ((q >> 7) + 1) << 7;

    __shared__ float buf[SS];
    __shared__ float red[256];
    const int tid = threadIdx.x;

    float mx = -3.0e38f;
    for (int i = tid; i < len; i += 256) {
        float v = row[i];
        buf[i] = v;
        mx = fmaxf(mx, v);
    }
    red[tid] = mx;
    __syncthreads();
    for (int s = 128; s > 0; s >>= 1) {
        if (tid < s) red[tid] = fmaxf(red[tid], red[tid + s]);
        __syncthreads();
    }
    const float m = red[0];
    __syncthreads();

    float sm = 0.f;
    for (int i = tid; i < len; i += 256) {
        float e = expf(buf[i] - m);
        buf[i] = e;
        sm += e;
    }
    red[tid] = sm;
    __syncthreads();
    for (int s = 128; s > 0; s >>= 1) {
        if (tid < s) red[tid] += red[tid + s];
        __syncthreads();
    }
    const float inv = 1.0f / red[0];

    for (int i = tid; i < len; i += 256)        row[i] = buf[i] * inv;
    for (int i = len + tid; i < kend; i += 256) row[i] = 0.0f;
}

// ---------------------------------------------------------------------------
// Kernel 5: out[b] = P[b] @ x[b], tf32 MMA, cp.async 3-stage pipeline.
// ONLY delta vs round-2 pv: global->smem via cp.async (raw fp32 bits), and
// the cvt.rna tf32 conversion moved to the fragment load (registers).
// Smem layout / fragment mapping / store: byte-identical to round-2 pv.
// ---------------------------------------------------------------------------
#define PV_STAGES 3
#define PV_AS 36
#define PV_BS 136
#define PV_STAGE_FLOATS (128 * PV_AS + 32 * PV_BS)   // 8960

__global__ void __launch_bounds__(256, 2) pv_mma_kernel(float* __restrict__ out)
{
    extern __shared__ float sm[];

    const int tid = threadIdx.x;
    const int n0 = blockIdx.x * 128;
    const int m0 = blockIdx.y * 128;
    const int b  = blockIdx.z;

    const float* P  = g_P + (size_t)b * SS * SS;
    const float* Xb = g_x + (size_t)b * SS * DD;
    const int ntiles = (m0 + 128) / 32;     // causal bound (>= 4 always)

    auto issue_tile = [&](int t) {
        const int stg = t % PV_STAGES;
        float* As = sm + stg * PV_STAGE_FLOATS;
        float* Bs = As + 128 * PV_AS;
        const int kt = t * 32;
        #pragma unroll
        for (int i = 0; i < 4; i++) {
            int idx = tid + i * 256;
            int r = idx >> 3, c = (idx & 7) * 4;
            const float* src = P + (size_t)(m0 + r) * SS + kt + c;
            uint32_t dst = (uint32_t)__cvta_generic_to_shared(As + r * PV_AS + c);
            asm volatile("cp.async.cg.shared.global [%0], [%1], 16;\n"
                         :: "r"(dst), "l"(src) : "memory");
        }
        #pragma unroll
        for (int i = 0; i < 4; i++) {
            int idx = tid + i * 256;
            int r = idx >> 5, c = (idx & 31) * 4;
            const float* src = Xb + (size_t)(kt + r) * DD + n0 + c;
            uint32_t dst = (uint32_t)__cvta_generic_to_shared(Bs + r * PV_BS + c);
            asm volatile("cp.async.cg.shared.global [%0], [%1], 16;\n"
                         :: "r"(dst), "l"(src) : "memory");
        }
    };

    // prologue: STAGES-1 tiles in flight
    #pragma unroll
    for (int t = 0; t < PV_STAGES - 1; t++) {
        issue_tile(t);
        asm volatile("cp.async.commit_group;\n" ::: "memory");
    }

    const int lane = tid & 31, wid = tid >> 5;
    const int wm = wid >> 2, wn = wid & 3;
    const int lr = lane >> 2, lc = lane & 3;

    float acc[4][4][4] = {};

    for (int t = 0; t < ntiles; t++) {
        if (t + PV_STAGES - 1 < ntiles) issue_tile(t + PV_STAGES - 1);
        asm volatile("cp.async.commit_group;\n" ::: "memory");
        asm volatile("cp.async.wait_group %0;\n" :: "n"(PV_STAGES - 1) : "memory");
        __syncthreads();

        const int stg = t % PV_STAGES;
        const float* As = sm + stg * PV_STAGE_FLOATS;
        const float* Bs = As + 128 * PV_AS;

        #pragma unroll
        for (int ks = 0; ks < 32; ks += 8) {
            uint32_t afrag[4][4];
            #pragma unroll
            for (int mt = 0; mt < 4; mt++) {
                int mrow = wm * 64 + mt * 16 + lr;
                afrag[mt][0] = f2tf32(As[(mrow    ) * PV_AS + ks + lc    ]);
                afrag[mt][1] = f2tf32(As[(mrow + 8) * PV_AS + ks + lc    ]);
                afrag[mt][2] = f2tf32(As[(mrow    ) * PV_AS + ks + lc + 4]);
                afrag[mt][3] = f2tf32(As[(mrow + 8) * PV_AS + ks + lc + 4]);
            }
            uint32_t bfrag[4][2];
            #pragma unroll
            for (int nt = 0; nt < 4; nt++) {
                int ncol = wn * 32 + nt * 8 + lr;
                bfrag[nt][0] = f2tf32(Bs[(ks + lc    ) * PV_BS + ncol]);
                bfrag[nt][1] = f2tf32(Bs[(ks + lc + 4) * PV_BS + ncol]);
            }
            #pragma unroll
            for (int mt = 0; mt < 4; mt++)
                #pragma unroll
                for (int nt = 0; nt < 4; nt++)
                    mma_tf32(acc[mt][nt], afrag[mt], bfrag[nt]);
        }
        __syncthreads();
    }

    #pragma unroll
    for (int mt = 0; mt < 4; mt++) {
        int m = m0 + wm * 64 + mt * 16 + lr;
        #pragma unroll
        for (int nt = 0; nt < 4; nt++) {
            int n = n0 + wn * 32 + nt * 8 + lc * 2;
            float2 v0 = {acc[mt][nt][0], acc[mt][nt][1]};
            float2 v1 = {acc[mt][nt][2], acc[mt][nt][3]};
            *(float2*)(out + (size_t)(b * SS + m    ) * DD + n) = v0;
            *(float2*)(out + (size_t)(b * SS + m + 8) * DD + n) = v1;
        }
    }
}

// ---------------------------------------------------------------------------
// Host launch (graph-capturable: kernel launches only; no static guards)
// ---------------------------------------------------------------------------
extern "C" void kernel_launch(void* const* d_in, const int* in_sizes, int n_in,
                              void* d_out, int out_size)
{
    const float* X  = (const float*)d_in[0];
    const float* Wq = (const float*)d_in[1];
    const float* Wk = (const float*)d_in[2];
    const float* Wv = (const float*)d_in[3];
    const float* Wo = (const float*)d_in[4];
    float* out = (float*)d_out;

    const int pv_smem = PV_STAGES * PV_STAGE_FLOATS * 4;   // 107,520 bytes

    cudaFuncSetAttribute(pv_mma_kernel,
                         cudaFuncAttributeMaxDynamicSharedMemorySize, pv_smem);

    proj_kernel   <<<dim3(MTOT / 64, 1, 3), 256>>>(X, Wq, Wk, Wv);
    xo_kernel     <<<dim3(DD / 64, MTOT / 64), 256>>>(Wo);
    scores_kernel <<<dim3(SS / 64, SS / 64, BB), 256>>>();
    softmax_kernel<<<MTOT, 256>>>();
    pv_mma_kernel <<<dim3(DD / 128, SS / 128, BB), 256, pv_smem>>>(out);
}

// round 5
// speedup vs baseline: 2.3222x; 1.1213x over previous
#include <cuda_runtime.h>
#include <cstdint>

// Problem dims
#define BB 4
#define SS 2048
#define DD 1024
#define HH 64
#define MTOT (BB * SS)   // 8192

// Scratch (device globals — no allocation allowed)
__device__ float g_q [MTOT * HH];
__device__ float g_k [MTOT * HH];
__device__ float g_xv[MTOT * HH];
__device__ float g_x [(size_t)MTOT * DD];     // tf32-clean after xo
__device__ float g_P [(size_t)BB * SS * SS];  // tf32-clean after softmax

__device__ __forceinline__ uint32_t f2tf32(float f) {
    uint32_t u;
    asm("cvt.rna.tf32.f32 %0, %1;" : "=r"(u) : "f"(f));
    return u;
}
__device__ __forceinline__ void split_tf32(float v, float& h, float& l) {
    uint32_t hu; asm("cvt.rna.tf32.f32 %0, %1;" : "=r"(hu) : "f"(v));
    h = __uint_as_float(hu);
    float r = v - h;
    uint32_t lu; asm("cvt.rna.tf32.f32 %0, %1;" : "=r"(lu) : "f"(r));
    l = __uint_as_float(lu);
}
__device__ __forceinline__ void mma_tf32(float* c, const uint32_t* a, const uint32_t* b) {
    asm volatile("mma.sync.aligned.m16n8k8.row.col.f32.tf32.tf32.f32 "
        "{%0,%1,%2,%3}, {%4,%5,%6,%7}, {%8,%9}, {%0,%1,%2,%3};"
        : "+f"(c[0]), "+f"(c[1]), "+f"(c[2]), "+f"(c[3])
        : "r"(a[0]), "r"(a[1]), "r"(a[2]), "r"(a[3]), "r"(b[0]), "r"(b[1]));
}

// ---------------------------------------------------------------------------
// Kernel 1: projections via 3xTF32 MMA (near-fp32 precision).
// z=0 -> q, z=1 -> k, z=2 -> xv.  C[8192,64] = X[8192,1024] @ W[1024,64].
// BM=128, BN=64, BK=32. 8 warps 4x2; warp tile 32x32 (2 mt x 4 nt).
// A stride 36 (tile 128x32), W stride 72 (tile 32x64) — both conflict-free.
// ---------------------------------------------------------------------------
#define PJ_XS 36
#define PJ_WS 72
__global__ void __launch_bounds__(256) proj_mma_kernel(
    const float* __restrict__ X,
    const float* __restrict__ Wq,
    const float* __restrict__ Wk,
    const float* __restrict__ Wv)
{
    extern __shared__ float sm[];
    float* Xh = sm;                    // [128][36]
    float* Xl = Xh + 128 * PJ_XS;
    float* Wh = Xl + 128 * PJ_XS;      // [32][72]
    float* Wl = Wh + 32 * PJ_WS;

    const int tid = threadIdx.x;
    const int m0  = blockIdx.x * 128;
    const float* W   = (blockIdx.z == 0) ? Wq : (blockIdx.z == 1) ? Wk : Wv;
    float*       out = (blockIdx.z == 0) ? g_q : (blockIdx.z == 1) ? g_k : g_xv;

    const int lane = tid & 31, wid = tid >> 5;
    const int wm = wid >> 1;          // 0..3
    const int wn = wid & 1;           // 0..1
    const int lr = lane >> 2, lc = lane & 3;

    float acc[2][4][4] = {};

    for (int k0 = 0; k0 < DD; k0 += 32) {
        #pragma unroll
        for (int i = 0; i < 4; i++) {         // X tile 128x32
            int idx = tid + i * 256;
            int r = idx >> 3, c = (idx & 7) * 4;
            float4 v = *(const float4*)(X + (size_t)(m0 + r) * DD + k0 + c);
            float4 h, l;
            split_tf32(v.x, h.x, l.x); split_tf32(v.y, h.y, l.y);
            split_tf32(v.z, h.z, l.z); split_tf32(v.w, h.w, l.w);
            *(float4*)(Xh + r * PJ_XS + c) = h;
            *(float4*)(Xl + r * PJ_XS + c) = l;
        }
        #pragma unroll
        for (int i = 0; i < 2; i++) {         // W tile 32x64
            int idx = tid + i * 256;
            int r = idx >> 4, c = (idx & 15) * 4;
            float4 v = *(const float4*)(W + (size_t)(k0 + r) * HH + c);
            float4 h, l;
            split_tf32(v.x, h.x, l.x); split_tf32(v.y, h.y, l.y);
            split_tf32(v.z, h.z, l.z); split_tf32(v.w, h.w, l.w);
            *(float4*)(Wh + r * PJ_WS + c) = h;
            *(float4*)(Wl + r * PJ_WS + c) = l;
        }
        __syncthreads();

        #pragma unroll
        for (int ks = 0; ks < 32; ks += 8) {
            uint32_t ah[2][4], al[2][4];
            #pragma unroll
            for (int mt = 0; mt < 2; mt++) {
                int mrow = wm * 32 + mt * 16 + lr;
                ah[mt][0] = __float_as_uint(Xh[(mrow    ) * PJ_XS + ks + lc    ]);
                ah[mt][1] = __float_as_uint(Xh[(mrow + 8) * PJ_XS + ks + lc    ]);
                ah[mt][2] = __float_as_uint(Xh[(mrow    ) * PJ_XS + ks + lc + 4]);
                ah[mt][3] = __float_as_uint(Xh[(mrow + 8) * PJ_XS + ks + lc + 4]);
                al[mt][0] = __float_as_uint(Xl[(mrow    ) * PJ_XS + ks + lc    ]);
                al[mt][1] = __float_as_uint(Xl[(mrow + 8) * PJ_XS + ks + lc    ]);
                al[mt][2] = __float_as_uint(Xl[(mrow    ) * PJ_XS + ks + lc + 4]);
                al[mt][3] = __float_as_uint(Xl[(mrow + 8) * PJ_XS + ks + lc + 4]);
            }
            uint32_t bh[4][2], bl[4][2];
            #pragma unroll
            for (int nt = 0; nt < 4; nt++) {
                int ncol = wn * 32 + nt * 8 + lr;
                bh[nt][0] = __float_as_uint(Wh[(ks + lc    ) * PJ_WS + ncol]);
                bh[nt][1] = __float_as_uint(Wh[(ks + lc + 4) * PJ_WS + ncol]);
                bl[nt][0] = __float_as_uint(Wl[(ks + lc    ) * PJ_WS + ncol]);
                bl[nt][1] = __float_as_uint(Wl[(ks + lc + 4) * PJ_WS + ncol]);
            }
            #pragma unroll
            for (int mt = 0; mt < 2; mt++)
                #pragma unroll
                for (int nt = 0; nt < 4; nt++) {
                    mma_tf32(acc[mt][nt], ah[mt], bh[nt]);
                    mma_tf32(acc[mt][nt], ah[mt], bl[nt]);
                    mma_tf32(acc[mt][nt], al[mt], bh[nt]);
                }
        }
        __syncthreads();
    }

    #pragma unroll
    for (int mt = 0; mt < 2; mt++) {
        int m = m0 + wm * 32 + mt * 16 + lr;
        #pragma unroll
        for (int nt = 0; nt < 4; nt++) {
            int n = wn * 32 + nt * 8 + lc * 2;
            float2 v0 = {acc[mt][nt][0], acc[mt][nt][1]};
            float2 v1 = {acc[mt][nt][2], acc[mt][nt][3]};
            *(float2*)(out + (size_t)(m    ) * HH + n) = v0;
            *(float2*)(out + (size_t)(m + 8) * HH + n) = v1;
        }
    }
}

// ---------------------------------------------------------------------------
// Kernel 2: x = xv @ O^T via 3xTF32, output tf32-rounded.
// BM=128, BN=128, K=64 resident. 8 warps 2x4; warp 64x32 (4 mt x 4 nt).
// FIX vs round 3: A stride is 68 (tile is 128x64 — stride must cover K=64).
// ---------------------------------------------------------------------------
#define XO_AS 68
#define XO_BS 136
__global__ void __launch_bounds__(256, 1) xo_mma_kernel(const float* __restrict__ O)
{
    extern __shared__ float sm[];
    float* Ah = sm;                    // [128][68]
    float* Al = Ah + 128 * XO_AS;
    float* Bh = Al + 128 * XO_AS;      // [64][136]
    float* Bl = Bh + 64 * XO_BS;

    const int tid = threadIdx.x;
    const int e0 = blockIdx.x * 128;
    const int m0 = blockIdx.y * 128;

    #pragma unroll
    for (int i = 0; i < 8; i++) {      // xv tile 128x64
        int idx = tid + i * 256;
        int r = idx >> 4, c = (idx & 15) * 4;
        float4 v = *(const float4*)(g_xv + (size_t)(m0 + r) * HH + c);
        float4 h, l;
        split_tf32(v.x, h.x, l.x); split_tf32(v.y, h.y, l.y);
        split_tf32(v.z, h.z, l.z); split_tf32(v.w, h.w, l.w);
        *(float4*)(Ah + r * XO_AS + c) = h;
        *(float4*)(Al + r * XO_AS + c) = l;
    }
    #pragma unroll
    for (int i = 0; i < 8; i++) {      // O tile: [e 128][h 64] -> Bh[h][e]
        int idx = tid + i * 256;
        int e = idx & 127, hc = (idx >> 7) * 4;
        float4 v = *(const float4*)(O + (size_t)(e0 + e) * HH + hc);
        float hx, lx;
        split_tf32(v.x, hx, lx); Bh[(hc + 0) * XO_BS + e] = hx; Bl[(hc + 0) * XO_BS + e] = lx;
        split_tf32(v.y, hx, lx); Bh[(hc + 1) * XO_BS + e] = hx; Bl[(hc + 1) * XO_BS + e] = lx;
        split_tf32(v.z, hx, lx); Bh[(hc + 2) * XO_BS + e] = hx; Bl[(hc + 2) * XO_BS + e] = lx;
        split_tf32(v.w, hx, lx); Bh[(hc + 3) * XO_BS + e] = hx; Bl[(hc + 3) * XO_BS + e] = lx;
    }
    __syncthreads();

    const int lane = tid & 31, wid = tid >> 5;
    const int wm = wid >> 2, wn = wid & 3;
    const int lr = lane >> 2, lc = lane & 3;

    float acc[4][4][4] = {};

    #pragma unroll
    for (int ks = 0; ks < 64; ks += 8) {
        uint32_t ah[4][4], al[4][4], bf[4][2];
        #pragma unroll
        for (int mt = 0; mt < 4; mt++) {
            int mrow = wm * 64 + mt * 16 + lr;
            ah[mt][0] = __float_as_uint(Ah[(mrow    ) * XO_AS + ks + lc    ]);
            ah[mt][1] = __float_as_uint(Ah[(mrow + 8) * XO_AS + ks + lc    ]);
            ah[mt][2] = __float_as_uint(Ah[(mrow    ) * XO_AS + ks + lc + 4]);
            ah[mt][3] = __float_as_uint(Ah[(mrow + 8) * XO_AS + ks + lc + 4]);
            al[mt][0] = __float_as_uint(Al[(mrow    ) * XO_AS + ks + lc    ]);
            al[mt][1] = __float_as_uint(Al[(mrow + 8) * XO_AS + ks + lc    ]);
            al[mt][2] = __float_as_uint(Al[(mrow    ) * XO_AS + ks + lc + 4]);
            al[mt][3] = __float_as_uint(Al[(mrow + 8) * XO_AS + ks + lc + 4]);
        }
        #pragma unroll
        for (int nt = 0; nt < 4; nt++) {
            int ncol = wn * 32 + nt * 8 + lr;
            bf[nt][0] = __float_as_uint(Bh[(ks + lc    ) * XO_BS + ncol]);
            bf[nt][1] = __float_as_uint(Bh[(ks + lc + 4) * XO_BS + ncol]);
        }
        #pragma unroll
        for (int mt = 0; mt < 4; mt++)
            #pragma unroll
            for (int nt = 0; nt < 4; nt++) {
                mma_tf32(acc[mt][nt], ah[mt], bf[nt]);
                mma_tf32(acc[mt][nt], al[mt], bf[nt]);
            }
        #pragma unroll
        for (int nt = 0; nt < 4; nt++) {
            int ncol = wn * 32 + nt * 8 + lr;
            bf[nt][0] = __float_as_uint(Bl[(ks + lc    ) * XO_BS + ncol]);
            bf[nt][1] = __float_as_uint(Bl[(ks + lc + 4) * XO_BS + ncol]);
        }
        #pragma unroll
        for (int mt = 0; mt < 4; mt++)
            #pragma unroll
            for (int nt = 0; nt < 4; nt++)
                mma_tf32(acc[mt][nt], ah[mt], bf[nt]);
    }

    #pragma unroll
    for (int mt = 0; mt < 4; mt++) {
        int m = m0 + wm * 64 + mt * 16 + lr;
        #pragma unroll
        for (int nt = 0; nt < 4; nt++) {
            int n = e0 + wn * 32 + nt * 8 + lc * 2;
            float2 v0 = {__uint_as_float(f2tf32(acc[mt][nt][0])),
                         __uint_as_float(f2tf32(acc[mt][nt][1]))};
            float2 v1 = {__uint_as_float(f2tf32(acc[mt][nt][2])),
                         __uint_as_float(f2tf32(acc[mt][nt][3]))};
            *(float2*)(g_x + (size_t)(m    ) * DD + n) = v0;
            *(float2*)(g_x + (size_t)(m + 8) * DD + n) = v1;
        }
    }
}

// ---------------------------------------------------------------------------
// Kernel 3: causal raw scores, fp32 SIMT (precision through exp)
// ---------------------------------------------------------------------------
__global__ void __launch_bounds__(256) scores_kernel()
{
    const int jt = blockIdx.x, it = blockIdx.y, b = blockIdx.z;
    if (jt > it) return;

    __shared__ float Qs[64][64];
    __shared__ float Ks[64][65];

    const int tid = threadIdx.x;
    const int i0 = it * 64, j0 = jt * 64;
    const int base = b * SS;

    for (int idx = tid; idx < 64 * 64; idx += 256) {
        int r = idx >> 6, c = idx & 63;
        Qs[r][c] = g_q[(size_t)(base + i0 + r) * HH + c];
        Ks[r][c] = g_k[(size_t)(base + j0 + r) * HH + c];
    }
    __syncthreads();

    const int tx = tid & 15, ty = tid >> 4;
    float acc[4][4] = {};

    #pragma unroll 8
    for (int h = 0; h < 64; h++) {
        float a[4], bb[4];
        #pragma unroll
        for (int i = 0; i < 4; i++) a[i]  = Qs[ty * 4 + i][h];
        #pragma unroll
        for (int j = 0; j < 4; j++) bb[j] = Ks[tx * 4 + j][h];
        #pragma unroll
        for (int i = 0; i < 4; i++)
            #pragma unroll
            for (int j = 0; j < 4; j++)
                acc[i][j] = fmaf(a[i], bb[j], acc[i][j]);
    }

    float* Pb = g_P + (size_t)b * SS * SS;
    #pragma unroll
    for (int i = 0; i < 4; i++) {
        int gi = i0 + ty * 4 + i;
        #pragma unroll
        for (int j = 0; j < 4; j++) {
            int gj = j0 + tx * 4 + j;
            if (gj <= gi)
                Pb[(size_t)gi * SS + gj] = acc[i][j];
        }
    }
}

// ---------------------------------------------------------------------------
// Kernel 4: row softmax; writes tf32-clean P; zero-fill pad to 128-boundary
// ---------------------------------------------------------------------------
__global__ void __launch_bounds__(256) softmax_kernel()
{
    const int g = blockIdx.x;
    const int q = g & (SS - 1);
    float* row = g_P + (size_t)g * SS;
    const int len  = q + 1;
    const int kend = ((q >> 7) + 1) << 7;

    __shared__ float buf[SS];
    __shared__ float red[256];
    const int tid = threadIdx.x;

    float mx = -3.0e38f;
    for (int i = tid; i < len; i += 256) {
        float v = row[i];
        buf[i] = v;
        mx = fmaxf(mx, v);
    }
    red[tid] = mx;
    __syncthreads();
    for (int s = 128; s > 0; s >>= 1) {
        if (tid < s) red[tid] = fmaxf(red[tid], red[tid + s]);
        __syncthreads();
    }
    const float m = red[0];
    __syncthreads();

    float sm = 0.f;
    for (int i = tid; i < len; i += 256) {
        float e = expf(buf[i] - m);
        buf[i] = e;
        sm += e;
    }
    red[tid] = sm;
    __syncthreads();
    for (int s = 128; s > 0; s >>= 1) {
        if (tid < s) red[tid] += red[tid + s];
        __syncthreads();
    }
    const float inv = 1.0f / red[0];

    for (int i = tid; i < len; i += 256)
        row[i] = __uint_as_float(f2tf32(buf[i] * inv));
    for (int i = len + tid; i < kend; i += 256) row[i] = 0.0f;
}

// ---------------------------------------------------------------------------
// Kernel 5: out[b] = P[b] @ x[b], tf32 MMA, cp.async 3-stage pipeline.
// Inputs tf32-clean -> raw-bit fragment loads (no cvt on critical path).
// ---------------------------------------------------------------------------
#define PV_STAGES 3
#define PV_AS 36
#define PV_BS 136
#define PV_STAGE_FLOATS (128 * PV_AS + 32 * PV_BS)   // 8960

__global__ void __launch_bounds__(256, 2) pv_mma_kernel(float* __restrict__ out)
{
    extern __shared__ float sm[];

    const int tid = threadIdx.x;
    const int n0 = blockIdx.x * 128;
    const int m0 = blockIdx.y * 128;
    const int b  = blockIdx.z;

    const float* P  = g_P + (size_t)b * SS * SS;
    const float* Xb = g_x + (size_t)b * SS * DD;
    const int ntiles = (m0 + 128) / 32;     // causal bound (>= 4 always)

    auto issue_tile = [&](int t) {
        const int stg = t % PV_STAGES;
        float* As = sm + stg * PV_STAGE_FLOATS;
        float* Bs = As + 128 * PV_AS;
        const int kt = t * 32;
        #pragma unroll
        for (int i = 0; i < 4; i++) {
            int idx = tid + i * 256;
            int r = idx >> 3, c = (idx & 7) * 4;
            const float* src = P + (size_t)(m0 + r) * SS + kt + c;
            uint32_t dst = (uint32_t)__cvta_generic_to_shared(As + r * PV_AS + c);
            asm volatile("cp.async.cg.shared.global [%0], [%1], 16;\n"
                         :: "r"(dst), "l"(src) : "memory");
        }
        #pragma unroll
        for (int i = 0; i < 4; i++) {
            int idx = tid + i * 256;
            int r = idx >> 5, c = (idx & 31) * 4;
            const float* src = Xb + (size_t)(kt + r) * DD + n0 + c;
            uint32_t dst = (uint32_t)__cvta_generic_to_shared(Bs + r * PV_BS + c);
            asm volatile("cp.async.cg.shared.global [%0], [%1], 16;\n"
                         :: "r"(dst), "l"(src) : "memory");
        }
    };

    #pragma unroll
    for (int t = 0; t < PV_STAGES - 1; t++) {
        issue_tile(t);
        asm volatile("cp.async.commit_group;\n" ::: "memory");
    }

    const int lane = tid & 31, wid = tid >> 5;
    const int wm = wid >> 2, wn = wid & 3;
    const int lr = lane >> 2, lc = lane & 3;

    float acc[4][4][4] = {};

    for (int t = 0; t < ntiles; t++) {
        if (t + PV_STAGES - 1 < ntiles) issue_tile(t + PV_STAGES - 1);
        asm volatile("cp.async.commit_group;\n" ::: "memory");
        asm volatile("cp.async.wait_group %0;\n" :: "n"(PV_STAGES - 1) : "memory");
        __syncthreads();

        const int stg = t % PV_STAGES;
        const float* As = sm + stg * PV_STAGE_FLOATS;
        const float* Bs = As + 128 * PV_AS;

        #pragma unroll
        for (int ks = 0; ks < 32; ks += 8) {
            uint32_t afrag[4][4];
            #pragma unroll
            for (int mt = 0; mt < 4; mt++) {
                int mrow = wm * 64 + mt * 16 + lr;
                afrag[mt][0] = __float_as_uint(As[(mrow    ) * PV_AS + ks + lc    ]);
                afrag[mt][1] = __float_as_uint(As[(mrow + 8) * PV_AS + ks + lc    ]);
                afrag[mt][2] = __float_as_uint(As[(mrow    ) * PV_AS + ks + lc + 4]);
                afrag[mt][3] = __float_as_uint(As[(mrow + 8) * PV_AS + ks + lc + 4]);
            }
            uint32_t bfrag[4][2];
            #pragma unroll
            for (int nt = 0; nt < 4; nt++) {
                int ncol = wn * 32 + nt * 8 + lr;
                bfrag[nt][0] = __float_as_uint(Bs[(ks + lc    ) * PV_BS + ncol]);
                bfrag[nt][1] = __float_as_uint(Bs[(ks + lc + 4) * PV_BS + ncol]);
            }
            #pragma unroll
            for (int mt = 0; mt < 4; mt++)
                #pragma unroll
                for (int nt = 0; nt < 4; nt++)
                    mma_tf32(acc[mt][nt], afrag[mt], bfrag[nt]);
        }
        __syncthreads();
    }

    #pragma unroll
    for (int mt = 0; mt < 4; mt++) {
        int m = m0 + wm * 64 + mt * 16 + lr;
        #pragma unroll
        for (int nt = 0; nt < 4; nt++) {
            int n = n0 + wn * 32 + nt * 8 + lc * 2;
            float2 v0 = {acc[mt][nt][0], acc[mt][nt][1]};
            float2 v1 = {acc[mt][nt][2], acc[mt][nt][3]};
            *(float2*)(out + (size_t)(b * SS + m    ) * DD + n) = v0;
            *(float2*)(out + (size_t)(b * SS + m + 8) * DD + n) = v1;
        }
    }
}

// ---------------------------------------------------------------------------
// Host launch (graph-capturable: kernel launches only; no static guards)
// ---------------------------------------------------------------------------
extern "C" void kernel_launch(void* const* d_in, const int* in_sizes, int n_in,
                              void* d_out, int out_size)
{
    const float* X  = (const float*)d_in[0];
    const float* Wq = (const float*)d_in[1];
    const float* Wk = (const float*)d_in[2];
    const float* Wv = (const float*)d_in[3];
    const float* Wo = (const float*)d_in[4];
    float* out = (float*)d_out;

    const int pj_smem = (2 * 128 * PJ_XS + 2 * 32 * PJ_WS) * 4;   //  55,296
    const int xo_smem = (2 * 128 * XO_AS + 2 * 64 * XO_BS) * 4;   // 139,264
    const int pv_smem = PV_STAGES * PV_STAGE_FLOATS * 4;          // 107,520

    cudaFuncSetAttribute(proj_mma_kernel, cudaFuncAttributeMaxDynamicSharedMemorySize, pj_smem);
    cudaFuncSetAttribute(xo_mma_kernel,   cudaFuncAttributeMaxDynamicSharedMemorySize, xo_smem);
    cudaFuncSetAttribute(pv_mma_kernel,   cudaFuncAttributeMaxDynamicSharedMemorySize, pv_smem);

    proj_mma_kernel<<<dim3(MTOT / 128, 1, 3), 256, pj_smem>>>(X, Wq, Wk, Wv);
    xo_mma_kernel  <<<dim3(DD / 128, MTOT / 128), 256, xo_smem>>>(Wo);
    scores_kernel  <<<dim3(SS / 64, SS / 64, BB), 256>>>();
    softmax_kernel <<<MTOT, 256>>>();
    pv_mma_kernel  <<<dim3(DD / 128, SS / 128, BB), 256, pv_smem>>>(out);
}

// round 6
// speedup vs baseline: 2.4258x; 1.0446x over previous
#include <cuda_runtime.h>
#include <cstdint>

// Problem dims
#define BB 4
#define SS 2048
#define DD 1024
#define HH 64
#define MTOT (BB * SS)   // 8192

// Scratch (device globals — no allocation allowed)
__device__ float g_q [MTOT * HH];
__device__ float g_k [MTOT * HH];
__device__ float g_xv[MTOT * HH];
__device__ float g_x [(size_t)MTOT * DD];     // tf32-clean after xo
__device__ float g_P [(size_t)BB * SS * SS];  // tf32-clean after softmax

__device__ __forceinline__ uint32_t f2tf32(float f) {
    uint32_t u;
    asm("cvt.rna.tf32.f32 %0, %1;" : "=r"(u) : "f"(f));
    return u;
}
__device__ __forceinline__ void split_tf32(float v, float& h, float& l) {
    uint32_t hu; asm("cvt.rna.tf32.f32 %0, %1;" : "=r"(hu) : "f"(v));
    h = __uint_as_float(hu);
    float r = v - h;
    uint32_t lu; asm("cvt.rna.tf32.f32 %0, %1;" : "=r"(lu) : "f"(r));
    l = __uint_as_float(lu);
}
__device__ __forceinline__ void mma_tf32(float* c, const uint32_t* a, const uint32_t* b) {
    asm volatile("mma.sync.aligned.m16n8k8.row.col.f32.tf32.tf32.f32 "
        "{%0,%1,%2,%3}, {%4,%5,%6,%7}, {%8,%9}, {%0,%1,%2,%3};"
        : "+f"(c[0]), "+f"(c[1]), "+f"(c[2]), "+f"(c[3])
        : "r"(a[0]), "r"(a[1]), "r"(a[2]), "r"(a[3]), "r"(b[0]), "r"(b[1]));
}

// ---------------------------------------------------------------------------
// Kernel 1: projections via 3xTF32 MMA (near-fp32 precision).  (unchanged)
// ---------------------------------------------------------------------------
#define PJ_XS 36
#define PJ_WS 72
__global__ void __launch_bounds__(256) proj_mma_kernel(
    const float* __restrict__ X,
    const float* __restrict__ Wq,
    const float* __restrict__ Wk,
    const float* __restrict__ Wv)
{
    extern __shared__ float sm[];
    float* Xh = sm;
    float* Xl = Xh + 128 * PJ_XS;
    float* Wh = Xl + 128 * PJ_XS;
    float* Wl = Wh + 32 * PJ_WS;

    const int tid = threadIdx.x;
    const int m0  = blockIdx.x * 128;
    const float* W   = (blockIdx.z == 0) ? Wq : (blockIdx.z == 1) ? Wk : Wv;
    float*       out = (blockIdx.z == 0) ? g_q : (blockIdx.z == 1) ? g_k : g_xv;

    const int lane = tid & 31, wid = tid >> 5;
    const int wm = wid >> 1;
    const int wn = wid & 1;
    const int lr = lane >> 2, lc = lane & 3;

    float acc[2][4][4] = {};

    for (int k0 = 0; k0 < DD; k0 += 32) {
        #pragma unroll
        for (int i = 0; i < 4; i++) {
            int idx = tid + i * 256;
            int r = idx >> 3, c = (idx & 7) * 4;
            float4 v = *(const float4*)(X + (size_t)(m0 + r) * DD + k0 + c);
            float4 h, l;
            split_tf32(v.x, h.x, l.x); split_tf32(v.y, h.y, l.y);
            split_tf32(v.z, h.z, l.z); split_tf32(v.w, h.w, l.w);
            *(float4*)(Xh + r * PJ_XS + c) = h;
            *(float4*)(Xl + r * PJ_XS + c) = l;
        }
        #pragma unroll
        for (int i = 0; i < 2; i++) {
            int idx = tid + i * 256;
            int r = idx >> 4, c = (idx & 15) * 4;
            float4 v = *(const float4*)(W + (size_t)(k0 + r) * HH + c);
            float4 h, l;
            split_tf32(v.x, h.x, l.x); split_tf32(v.y, h.y, l.y);
            split_tf32(v.z, h.z, l.z); split_tf32(v.w, h.w, l.w);
            *(float4*)(Wh + r * PJ_WS + c) = h;
            *(float4*)(Wl + r * PJ_WS + c) = l;
        }
        __syncthreads();

        #pragma unroll
        for (int ks = 0; ks < 32; ks += 8) {
            uint32_t ah[2][4], al[2][4];
            #pragma unroll
            for (int mt = 0; mt < 2; mt++) {
                int mrow = wm * 32 + mt * 16 + lr;
                ah[mt][0] = __float_as_uint(Xh[(mrow    ) * PJ_XS + ks + lc    ]);
                ah[mt][1] = __float_as_uint(Xh[(mrow + 8) * PJ_XS + ks + lc    ]);
                ah[mt][2] = __float_as_uint(Xh[(mrow    ) * PJ_XS + ks + lc + 4]);
                ah[mt][3] = __float_as_uint(Xh[(mrow + 8) * PJ_XS + ks + lc + 4]);
                al[mt][0] = __float_as_uint(Xl[(mrow    ) * PJ_XS + ks + lc    ]);
                al[mt][1] = __float_as_uint(Xl[(mrow + 8) * PJ_XS + ks + lc    ]);
                al[mt][2] = __float_as_uint(Xl[(mrow    ) * PJ_XS + ks + lc + 4]);
                al[mt][3] = __float_as_uint(Xl[(mrow + 8) * PJ_XS + ks + lc + 4]);
            }
            uint32_t bh[4][2], bl[4][2];
            #pragma unroll
            for (int nt = 0; nt < 4; nt++) {
                int ncol = wn * 32 + nt * 8 + lr;
                bh[nt][0] = __float_as_uint(Wh[(ks + lc    ) * PJ_WS + ncol]);
                bh[nt][1] = __float_as_uint(Wh[(ks + lc + 4) * PJ_WS + ncol]);
                bl[nt][0] = __float_as_uint(Wl[(ks + lc    ) * PJ_WS + ncol]);
                bl[nt][1] = __float_as_uint(Wl[(ks + lc + 4) * PJ_WS + ncol]);
            }
            #pragma unroll
            for (int mt = 0; mt < 2; mt++)
                #pragma unroll
                for (int nt = 0; nt < 4; nt++) {
                    mma_tf32(acc[mt][nt], ah[mt], bh[nt]);
                    mma_tf32(acc[mt][nt], ah[mt], bl[nt]);
                    mma_tf32(acc[mt][nt], al[mt], bh[nt]);
                }
        }
        __syncthreads();
    }

    #pragma unroll
    for (int mt = 0; mt < 2; mt++) {
        int m = m0 + wm * 32 + mt * 16 + lr;
        #pragma unroll
        for (int nt = 0; nt < 4; nt++) {
            int n = wn * 32 + nt * 8 + lc * 2;
            float2 v0 = {acc[mt][nt][0], acc[mt][nt][1]};
            float2 v1 = {acc[mt][nt][2], acc[mt][nt][3]};
            *(float2*)(out + (size_t)(m    ) * HH + n) = v0;
            *(float2*)(out + (size_t)(m + 8) * HH + n) = v1;
        }
    }
}

// ---------------------------------------------------------------------------
// Kernel 2: x = xv @ O^T via 3xTF32, output tf32-rounded.  (unchanged)
// ---------------------------------------------------------------------------
#define XO_AS 68
#define XO_BS 136
__global__ void __launch_bounds__(256, 1) xo_mma_kernel(const float* __restrict__ O)
{
    extern __shared__ float sm[];
    float* Ah = sm;
    float* Al = Ah + 128 * XO_AS;
    float* Bh = Al + 128 * XO_AS;
    float* Bl = Bh + 64 * XO_BS;

    const int tid = threadIdx.x;
    const int e0 = blockIdx.x * 128;
    const int m0 = blockIdx.y * 128;

    #pragma unroll
    for (int i = 0; i < 8; i++) {
        int idx = tid + i * 256;
        int r = idx >> 4, c = (idx & 15) * 4;
        float4 v = *(const float4*)(g_xv + (size_t)(m0 + r) * HH + c);
        float4 h, l;
        split_tf32(v.x, h.x, l.x); split_tf32(v.y, h.y, l.y);
        split_tf32(v.z, h.z, l.z); split_tf32(v.w, h.w, l.w);
        *(float4*)(Ah + r * XO_AS + c) = h;
        *(float4*)(Al + r * XO_AS + c) = l;
    }
    #pragma unroll
    for (int i = 0; i < 8; i++) {
        int idx = tid + i * 256;
        int e = idx & 127, hc = (idx >> 7) * 4;
        float4 v = *(const float4*)(O + (size_t)(e0 + e) * HH + hc);
        float hx, lx;
        split_tf32(v.x, hx, lx); Bh[(hc + 0) * XO_BS + e] = hx; Bl[(hc + 0) * XO_BS + e] = lx;
        split_tf32(v.y, hx, lx); Bh[(hc + 1) * XO_BS + e] = hx; Bl[(hc + 1) * XO_BS + e] = lx;
        split_tf32(v.z, hx, lx); Bh[(hc + 2) * XO_BS + e] = hx; Bl[(hc + 2) * XO_BS + e] = lx;
        split_tf32(v.w, hx, lx); Bh[(hc + 3) * XO_BS + e] = hx; Bl[(hc + 3) * XO_BS + e] = lx;
    }
    __syncthreads();

    const int lane = tid & 31, wid = tid >> 5;
    const int wm = wid >> 2, wn = wid & 3;
    const int lr = lane >> 2, lc = lane & 3;

    float acc[4][4][4] = {};

    #pragma unroll
    for (int ks = 0; ks < 64; ks += 8) {
        uint32_t ah[4][4], al[4][4], bf[4][2];
        #pragma unroll
        for (int mt = 0; mt < 4; mt++) {
            int mrow = wm * 64 + mt * 16 + lr;
            ah[mt][0] = __float_as_uint(Ah[(mrow    ) * XO_AS + ks + lc    ]);
            ah[mt][1] = __float_as_uint(Ah[(mrow + 8) * XO_AS + ks + lc    ]);
            ah[mt][2] = __float_as_uint(Ah[(mrow    ) * XO_AS + ks + lc + 4]);
            ah[mt][3] = __float_as_uint(Ah[(mrow + 8) * XO_AS + ks + lc + 4]);
            al[mt][0] = __float_as_uint(Al[(mrow    ) * XO_AS + ks + lc    ]);
            al[mt][1] = __float_as_uint(Al[(mrow + 8) * XO_AS + ks + lc    ]);
            al[mt][2] = __float_as_uint(Al[(mrow    ) * XO_AS + ks + lc + 4]);
            al[mt][3] = __float_as_uint(Al[(mrow + 8) * XO_AS + ks + lc + 4]);
        }
        #pragma unroll
        for (int nt = 0; nt < 4; nt++) {
            int ncol = wn * 32 + nt * 8 + lr;
            bf[nt][0] = __float_as_uint(Bh[(ks + lc    ) * XO_BS + ncol]);
            bf[nt][1] = __float_as_uint(Bh[(ks + lc + 4) * XO_BS + ncol]);
        }
        #pragma unroll
        for (int mt = 0; mt < 4; mt++)
            #pragma unroll
            for (int nt = 0; nt < 4; nt++) {
                mma_tf32(acc[mt][nt], ah[mt], bf[nt]);
                mma_tf32(acc[mt][nt], al[mt], bf[nt]);
            }
        #pragma unroll
        for (int nt = 0; nt < 4; nt++) {
            int ncol = wn * 32 + nt * 8 + lr;
            bf[nt][0] = __float_as_uint(Bl[(ks + lc    ) * XO_BS + ncol]);
            bf[nt][1] = __float_as_uint(Bl[(ks + lc + 4) * XO_BS + ncol]);
        }
        #pragma unroll
        for (int mt = 0; mt < 4; mt++)
            #pragma unroll
            for (int nt = 0; nt < 4; nt++)
                mma_tf32(acc[mt][nt], ah[mt], bf[nt]);
    }

    #pragma unroll
    for (int mt = 0; mt < 4; mt++) {
        int m = m0 + wm * 64 + mt * 16 + lr;
        #pragma unroll
        for (int nt = 0; nt < 4; nt++) {
            int n = e0 + wn * 32 + nt * 8 + lc * 2;
            float2 v0 = {__uint_as_float(f2tf32(acc[mt][nt][0])),
                         __uint_as_float(f2tf32(acc[mt][nt][1]))};
            float2 v1 = {__uint_as_float(f2tf32(acc[mt][nt][2])),
                         __uint_as_float(f2tf32(acc[mt][nt][3]))};
            *(float2*)(g_x + (size_t)(m    ) * DD + n) = v0;
            *(float2*)(g_x + (size_t)(m + 8) * DD + n) = v1;
        }
    }
}

// ---------------------------------------------------------------------------
// Kernel 3 (NEW): causal scores via 3xTF32 MMA (xo_mma structure).
// P[i,j] = q[i,:]·k[j,:], j<=i.  BM=128(i), BN=128(j), K=64 resident.
// Interior tiles (jt<it): vectorized stores. Diagonal: per-element mask.
// ---------------------------------------------------------------------------
__global__ void __launch_bounds__(256, 1) scores_mma_kernel()
{
    const int jt = blockIdx.x, it = blockIdx.y, b = blockIdx.z;
    if (jt > it) return;

    extern __shared__ float sm[];
    float* Ah = sm;                    // q tile [128][68]
    float* Al = Ah + 128 * XO_AS;
    float* Bh = Al + 128 * XO_AS;      // k^T tile [64][136]
    float* Bl = Bh + 64 * XO_BS;

    const int tid = threadIdx.x;
    const int i0 = it * 128, j0 = jt * 128;
    const int base = b * SS;

    #pragma unroll
    for (int i = 0; i < 8; i++) {      // q tile 128x64 (m-major)
        int idx = tid + i * 256;
        int r = idx >> 4, c = (idx & 15) * 4;
        float4 v = *(const float4*)(g_q + (size_t)(base + i0 + r) * HH + c);
        float4 h, l;
        split_tf32(v.x, h.x, l.x); split_tf32(v.y, h.y, l.y);
        split_tf32(v.z, h.z, l.z); split_tf32(v.w, h.w, l.w);
        *(float4*)(Ah + r * XO_AS + c) = h;
        *(float4*)(Al + r * XO_AS + c) = l;
    }
    #pragma unroll
    for (int i = 0; i < 8; i++) {      // k tile: [j 128][h 64] -> Bh[h][j]
        int idx = tid + i * 256;
        int j = idx & 127, hc = (idx >> 7) * 4;
        float4 v = *(const float4*)(g_k + (size_t)(base + j0 + j) * HH + hc);
        float hx, lx;
        split_tf32(v.x, hx, lx); Bh[(hc + 0) * XO_BS + j] = hx; Bl[(hc + 0) * XO_BS + j] = lx;
        split_tf32(v.y, hx, lx); Bh[(hc + 1) * XO_BS + j] = hx; Bl[(hc + 1) * XO_BS + j] = lx;
        split_tf32(v.z, hx, lx); Bh[(hc + 2) * XO_BS + j] = hx; Bl[(hc + 2) * XO_BS + j] = lx;
        split_tf32(v.w, hx, lx); Bh[(hc + 3) * XO_BS + j] = hx; Bl[(hc + 3) * XO_BS + j] = lx;
    }
    __syncthreads();

    const int lane = tid & 31, wid = tid >> 5;
    const int wm = wid >> 2, wn = wid & 3;
    const int lr = lane >> 2, lc = lane & 3;

    float acc[4][4][4] = {};

    #pragma unroll
    for (int ks = 0; ks < 64; ks += 8) {
        uint32_t ah[4][4], al[4][4], bf[4][2];
        #pragma unroll
        for (int mt = 0; mt < 4; mt++) {
            int mrow = wm * 64 + mt * 16 + lr;
            ah[mt][0] = __float_as_uint(Ah[(mrow    ) * XO_AS + ks + lc    ]);
            ah[mt][1] = __float_as_uint(Ah[(mrow + 8) * XO_AS + ks + lc    ]);
            ah[mt][2] = __float_as_uint(Ah[(mrow    ) * XO_AS + ks + lc + 4]);
            ah[mt][3] = __float_as_uint(Ah[(mrow + 8) * XO_AS + ks + lc + 4]);
            al[mt][0] = __float_as_uint(Al[(mrow    ) * XO_AS + ks + lc    ]);
            al[mt][1] = __float_as_uint(Al[(mrow + 8) * XO_AS + ks + lc    ]);
            al[mt][2] = __float_as_uint(Al[(mrow    ) * XO_AS + ks + lc + 4]);
            al[mt][3] = __float_as_uint(Al[(mrow + 8) * XO_AS + ks + lc + 4]);
        }
        #pragma unroll
        for (int nt = 0; nt < 4; nt++) {
            int ncol = wn * 32 + nt * 8 + lr;
            bf[nt][0] = __float_as_uint(Bh[(ks + lc    ) * XO_BS + ncol]);
            bf[nt][1] = __float_as_uint(Bh[(ks + lc + 4) * XO_BS + ncol]);
        }
        #pragma unroll
        for (int mt = 0; mt < 4; mt++)
            #pragma unroll
            for (int nt = 0; nt < 4; nt++) {
                mma_tf32(acc[mt][nt], ah[mt], bf[nt]);
                mma_tf32(acc[mt][nt], al[mt], bf[nt]);
            }
        #pragma unroll
        for (int nt = 0; nt < 4; nt++) {
            int ncol = wn * 32 + nt * 8 + lr;
            bf[nt][0] = __float_as_uint(Bl[(ks + lc    ) * XO_BS + ncol]);
            bf[nt][1] = __float_as_uint(Bl[(ks + lc + 4) * XO_BS + ncol]);
        }
        #pragma unroll
        for (int mt = 0; mt < 4; mt++)
            #pragma unroll
            for (int nt = 0; nt < 4; nt++)
                mma_tf32(acc[mt][nt], ah[mt], bf[nt]);
    }

    float* Pb = g_P + (size_t)b * SS * SS;
    if (jt < it) {
        // interior: all entries causal-valid -> vectorized stores
        #pragma unroll
        for (int mt = 0; mt < 4; mt++) {
            int gi = i0 + wm * 64 + mt * 16 + lr;
            #pragma unroll
            for (int nt = 0; nt < 4; nt++) {
                int gj = j0 + wn * 32 + nt * 8 + lc * 2;
                float2 v0 = {acc[mt][nt][0], acc[mt][nt][1]};
                float2 v1 = {acc[mt][nt][2], acc[mt][nt][3]};
                *(float2*)(Pb + (size_t)(gi    ) * SS + gj) = v0;
                *(float2*)(Pb + (size_t)(gi + 8) * SS + gj) = v1;
            }
        }
    } else {
        // diagonal: per-element causal mask
        #pragma unroll
        for (int mt = 0; mt < 4; mt++) {
            int gi = i0 + wm * 64 + mt * 16 + lr;
            #pragma unroll
            for (int nt = 0; nt < 4; nt++) {
                int gj = j0 + wn * 32 + nt * 8 + lc * 2;
                if (gj     <= gi    ) Pb[(size_t)(gi    ) * SS + gj    ] = acc[mt][nt][0];
                if (gj + 1 <= gi    ) Pb[(size_t)(gi    ) * SS + gj + 1] = acc[mt][nt][1];
                if (gj     <= gi + 8) Pb[(size_t)(gi + 8) * SS + gj    ] = acc[mt][nt][2];
                if (gj + 1 <= gi + 8) Pb[(size_t)(gi + 8) * SS + gj + 1] = acc[mt][nt][3];
            }
        }
    }
}

// ---------------------------------------------------------------------------
// Kernel 4: row softmax, float4-vectorized, __expf, shuffle reductions.
// Writes tf32-clean P; zero-fills pad up to next 128-boundary.
// ---------------------------------------------------------------------------
__global__ void __launch_bounds__(256) softmax_kernel()
{
    const int g = blockIdx.x;
    const int q = g & (SS - 1);
    float* row = g_P + (size_t)g * SS;
    const int len  = q + 1;
    const int len4 = len & ~3;
    const int kend = ((q >> 7) + 1) << 7;

    __shared__ float buf[SS];
    __shared__ float red[8];
    const int tid  = threadIdx.x;
    const int lane = tid & 31, wid = tid >> 5;

    // pass 1: load (vectorized) + max
    float mx = -3.0e38f;
    for (int i = tid * 4; i < len4; i += 1024) {
        float4 v = *(const float4*)(row + i);
        *(float4*)(buf + i) = v;
        mx = fmaxf(fmaxf(fmaxf(mx, v.x), v.y), fmaxf(v.z, v.w));
    }
    for (int i = len4 + tid; i < len; i += 256) {
        float v = row[i];
        buf[i] = v;
        mx = fmaxf(mx, v);
    }
    #pragma unroll
    for (int o = 16; o > 0; o >>= 1) mx = fmaxf(mx, __shfl_xor_sync(0xffffffffu, mx, o));
    if (lane == 0) red[wid] = mx;
    __syncthreads();
    float m = fmaxf(fmaxf(fmaxf(red[0], red[1]), fmaxf(red[2], red[3])),
                    fmaxf(fmaxf(red[4], red[5]), fmaxf(red[6], red[7])));
    __syncthreads();

    // pass 2: exp + sum
    float sm = 0.f;
    for (int i = tid * 4; i < len4; i += 1024) {
        float4 v = *(const float4*)(buf + i);
        v.x = __expf(v.x - m); v.y = __expf(v.y - m);
        v.z = __expf(v.z - m); v.w = __expf(v.w - m);
        *(float4*)(buf + i) = v;
        sm += (v.x + v.y) + (v.z + v.w);
    }
    for (int i = len4 + tid; i < len; i += 256) {
        float e = __expf(buf[i] - m);
        buf[i] = e;
        sm += e;
    }
    #pragma unroll
    for (int o = 16; o > 0; o >>= 1) sm += __shfl_xor_sync(0xffffffffu, sm, o);
    if (lane == 0) red[wid] = sm;
    __syncthreads();
    const float inv = 1.0f / (((red[0] + red[1]) + (red[2] + red[3])) +
                              ((red[4] + red[5]) + (red[6] + red[7])));

    // pass 3: normalize (tf32-clean) + write + zero-fill pad
    for (int i = tid * 4; i < len4; i += 1024) {
        float4 v = *(const float4*)(buf + i);
        v.x = __uint_as_float(f2tf32(v.x * inv));
        v.y = __uint_as_float(f2tf32(v.y * inv));
        v.z = __uint_as_float(f2tf32(v.z * inv));
        v.w = __uint_as_float(f2tf32(v.w * inv));
        *(float4*)(row + i) = v;
    }
    for (int i = len4 + tid; i < len; i += 256)
        row[i] = __uint_as_float(f2tf32(buf[i] * inv));
    for (int i = len + tid; i < kend; i += 256)
        row[i] = 0.0f;
}

// ---------------------------------------------------------------------------
// Kernel 5: out[b] = P[b] @ x[b], tf32 MMA, cp.async 3-stage.  (unchanged)
// ---------------------------------------------------------------------------
#define PV_STAGES 3
#define PV_AS 36
#define PV_BS 136
#define PV_STAGE_FLOATS (128 * PV_AS + 32 * PV_BS)   // 8960

__global__ void __launch_bounds__(256, 2) pv_mma_kernel(float* __restrict__ out)
{
    extern __shared__ float sm[];

    const int tid = threadIdx.x;
    const int n0 = blockIdx.x * 128;
    const int m0 = blockIdx.y * 128;
    const int b  = blockIdx.z;

    const float* P  = g_P + (size_t)b * SS * SS;
    const float* Xb = g_x + (size_t)b * SS * DD;
    const int ntiles = (m0 + 128) / 32;

    auto issue_tile = [&](int t) {
        const int stg = t % PV_STAGES;
        float* As = sm + stg * PV_STAGE_FLOATS;
        float* Bs = As + 128 * PV_AS;
        const int kt = t * 32;
        #pragma unroll
        for (int i = 0; i < 4; i++) {
            int idx = tid + i * 256;
            int r = idx >> 3, c = (idx & 7) * 4;
            const float* src = P + (size_t)(m0 + r) * SS + kt + c;
            uint32_t dst = (uint32_t)__cvta_generic_to_shared(As + r * PV_AS + c);
            asm volatile("cp.async.cg.shared.global [%0], [%1], 16;\n"
                         :: "r"(dst), "l"(src) : "memory");
        }
        #pragma unroll
        for (int i = 0; i < 4; i++) {
            int idx = tid + i * 256;
            int r = idx >> 5, c = (idx & 31) * 4;
            const float* src = Xb + (size_t)(kt + r) * DD + n0 + c;
            uint32_t dst = (uint32_t)__cvta_generic_to_shared(Bs + r * PV_BS + c);
            asm volatile("cp.async.cg.shared.global [%0], [%1], 16;\n"
                         :: "r"(dst), "l"(src) : "memory");
        }
    };

    #pragma unroll
    for (int t = 0; t < PV_STAGES - 1; t++) {
        issue_tile(t);
        asm volatile("cp.async.commit_group;\n" ::: "memory");
    }

    const int lane = tid & 31, wid = tid >> 5;
    const int wm = wid >> 2, wn = wid & 3;
    const int lr = lane >> 2, lc = lane & 3;

    float acc[4][4][4] = {};

    for (int t = 0; t < ntiles; t++) {
        if (t + PV_STAGES - 1 < ntiles) issue_tile(t + PV_STAGES - 1);
        asm volatile("cp.async.commit_group;\n" ::: "memory");
        asm volatile("cp.async.wait_group %0;\n" :: "n"(PV_STAGES - 1) : "memory");
        __syncthreads();

        const int stg = t % PV_STAGES;
        const float* As = sm + stg * PV_STAGE_FLOATS;
        const float* Bs = As + 128 * PV_AS;

        #pragma unroll
        for (int ks = 0; ks < 32; ks += 8) {
            uint32_t afrag[4][4];
            #pragma unroll
            for (int mt = 0; mt < 4; mt++) {
                int mrow = wm * 64 + mt * 16 + lr;
                afrag[mt][0] = __float_as_uint(As[(mrow    ) * PV_AS + ks + lc    ]);
                afrag[mt][1] = __float_as_uint(As[(mrow + 8) * PV_AS + ks + lc    ]);
                afrag[mt][2] = __float_as_uint(As[(mrow    ) * PV_AS + ks + lc + 4]);
                afrag[mt][3] = __float_as_uint(As[(mrow + 8) * PV_AS + ks + lc + 4]);
            }
            uint32_t bfrag[4][2];
            #pragma unroll
            for (int nt = 0; nt < 4; nt++) {
                int ncol = wn * 32 + nt * 8 + lr;
                bfrag[nt][0] = __float_as_uint(Bs[(ks + lc    ) * PV_BS + ncol]);
                bfrag[nt][1] = __float_as_uint(Bs[(ks + lc + 4) * PV_BS + ncol]);
            }
            #pragma unroll
            for (int mt = 0; mt < 4; mt++)
                #pragma unroll
                for (int nt = 0; nt < 4; nt++)
                    mma_tf32(acc[mt][nt], afrag[mt], bfrag[nt]);
        }
        __syncthreads();
    }

    #pragma unroll
    for (int mt = 0; mt < 4; mt++) {
        int m = m0 + wm * 64 + mt * 16 + lr;
        #pragma unroll
        for (int nt = 0; nt < 4; nt++) {
            int n = n0 + wn * 32 + nt * 8 + lc * 2;
            float2 v0 = {acc[mt][nt][0], acc[mt][nt][1]};
            float2 v1 = {acc[mt][nt][2], acc[mt][nt][3]};
            *(float2*)(out + (size_t)(b * SS + m    ) * DD + n) = v0;
            *(float2*)(out + (size_t)(b * SS + m + 8) * DD + n) = v1;
        }
    }
}

// ---------------------------------------------------------------------------
// Host launch (graph-capturable: kernel launches only)
// ---------------------------------------------------------------------------
extern "C" void kernel_launch(void* const* d_in, const int* in_sizes, int n_in,
                              void* d_out, int out_size)
{
    const float* X  = (const float*)d_in[0];
    const float* Wq = (const float*)d_in[1];
    const float* Wk = (const float*)d_in[2];
    const float* Wv = (const float*)d_in[3];
    const float* Wo = (const float*)d_in[4];
    float* out = (float*)d_out;

    const int pj_smem = (2 * 128 * PJ_XS + 2 * 32 * PJ_WS) * 4;   //  55,296
    const int xo_smem = (2 * 128 * XO_AS + 2 * 64 * XO_BS) * 4;   // 139,264
    const int pv_smem = PV_STAGES * PV_STAGE_FLOATS * 4;          // 107,520

    cudaFuncSetAttribute(proj_mma_kernel,   cudaFuncAttributeMaxDynamicSharedMemorySize, pj_smem);
    cudaFuncSetAttribute(xo_mma_kernel,     cudaFuncAttributeMaxDynamicSharedMemorySize, xo_smem);
    cudaFuncSetAttribute(scores_mma_kernel, cudaFuncAttributeMaxDynamicSharedMemorySize, xo_smem);
    cudaFuncSetAttribute(pv_mma_kernel,     cudaFuncAttributeMaxDynamicSharedMemorySize, pv_smem);

    proj_mma_kernel  <<<dim3(MTOT / 128, 1, 3), 256, pj_smem>>>(X, Wq, Wk, Wv);
    xo_mma_kernel    <<<dim3(DD / 128, MTOT / 128), 256, xo_smem>>>(Wo);
    scores_mma_kernel<<<dim3(SS / 128, SS / 128, BB), 256, xo_smem>>>();
    softmax_kernel   <<<MTOT, 256>>>();
    pv_mma_kernel    <<<dim3(DD / 128, SS / 128, BB), 256, pv_smem>>>(out);
}